// round 2
// baseline (speedup 1.0000x reference)
#include <cuda_runtime.h>

// BilateralGrid apply: out = trilerp(grid, coords, luminance(pixel)) affine-applied to pixel.
// Shapes: pixels (B,H,W,3) f32, coords (B,H,W,2) f32, grid (16,16,8,12) f32.
// N = B*H*W = 8,294,400. One thread handles 4 pixels (vectorized float4 I/O).

static constexpr int SH = 16;
static constexpr int SW = 16;
static constexpr int SL = 8;

__device__ __forceinline__ void apply_one(
    float r, float g, float b, float cx, float cy,
    const float* __restrict__ grid,
    float& or_, float& og_, float& ob_)
{
    float guide = 0.2126f * r + 0.7152f * g + 0.0722f * b;

    float gx = fminf(fmaxf(cx * (SW - 1), 0.0f), SW - 1.001f);
    float gy = fminf(fmaxf(cy * (SH - 1), 0.0f), SH - 1.001f);
    float gcl = fminf(fmaxf(guide, 0.0f), 1.0f);
    float gz = fminf(fmaxf(gcl * (SL - 1), 0.0f), SL - 1.001f);

    int x0 = (int)gx;   // values are non-negative -> trunc == floor
    int y0 = (int)gy;
    int z0 = (int)gz;
    int x1 = min(x0 + 1, SW - 1);
    int y1 = min(y0 + 1, SH - 1);
    int z1 = min(z0 + 1, SL - 1);

    float fx = gx - (float)x0;
    float fy = gy - (float)y0;
    float fz = gz - (float)z0;
    float ex = 1.0f - fx, ey = 1.0f - fy, ez = 1.0f - fz;

    float a0 = 0.f, a1 = 0.f, a2 = 0.f, a3 = 0.f;
    float a4 = 0.f, a5 = 0.f, a6 = 0.f, a7 = 0.f;
    float a8 = 0.f, a9 = 0.f, a10 = 0.f, a11 = 0.f;

#define CORNER(Y, X, Z, Wt)                                                    \
    {                                                                          \
        const float4* cp =                                                     \
            (const float4*)(grid + (((Y) * SW + (X)) * SL + (Z)) * 12);        \
        float4 qa = __ldg(cp + 0);                                             \
        float4 qb = __ldg(cp + 1);                                             \
        float4 qc = __ldg(cp + 2);                                             \
        float w = (Wt);                                                        \
        a0 += w * qa.x;  a1 += w * qa.y;  a2  += w * qa.z;  a3  += w * qa.w;   \
        a4 += w * qb.x;  a5 += w * qb.y;  a6  += w * qb.z;  a7  += w * qb.w;   \
        a8 += w * qc.x;  a9 += w * qc.y;  a10 += w * qc.z;  a11 += w * qc.w;   \
    }

    CORNER(y0, x0, z0, ey * ex * ez);
    CORNER(y0, x0, z1, ey * ex * fz);
    CORNER(y0, x1, z0, ey * fx * ez);
    CORNER(y0, x1, z1, ey * fx * fz);
    CORNER(y1, x0, z0, fy * ex * ez);
    CORNER(y1, x0, z1, fy * ex * fz);
    CORNER(y1, x1, z0, fy * fx * ez);
    CORNER(y1, x1, z1, fy * fx * fz);
#undef CORNER

    or_ = a0 * r + a1 * g + a2 * b + a3;
    og_ = a4 * r + a5 * g + a6 * b + a7;
    ob_ = a8 * r + a9 * g + a10 * b + a11;
}

__global__ void __launch_bounds__(256)
bilateral_grid_kernel(const float4* __restrict__ px,   // 3 float4 per quad (12 floats = 4 px)
                      const float4* __restrict__ cd,   // 2 float4 per quad (8 floats = 4 px)
                      const float* __restrict__ grid,
                      float4* __restrict__ out,        // 3 float4 per quad
                      int nquads)
{
    int q = blockIdx.x * blockDim.x + threadIdx.x;
    if (q >= nquads) return;

    float4 p0 = px[q * 3 + 0];   // px0.rgb, px1.r
    float4 p1 = px[q * 3 + 1];   // px1.gb, px2.rg
    float4 p2 = px[q * 3 + 2];   // px2.b, px3.rgb
    float4 c0 = cd[q * 2 + 0];   // c0.xy, c1.xy
    float4 c1 = cd[q * 2 + 1];   // c2.xy, c3.xy

    float4 o0, o1, o2;

    // pixel 0: (p0.x, p0.y, p0.z), coord (c0.x, c0.y)
    apply_one(p0.x, p0.y, p0.z, c0.x, c0.y, grid, o0.x, o0.y, o0.z);
    // pixel 1: (p0.w, p1.x, p1.y), coord (c0.z, c0.w)
    apply_one(p0.w, p1.x, p1.y, c0.z, c0.w, grid, o0.w, o1.x, o1.y);
    // pixel 2: (p1.z, p1.w, p2.x), coord (c1.x, c1.y)
    apply_one(p1.z, p1.w, p2.x, c1.x, c1.y, grid, o1.z, o1.w, o2.x);
    // pixel 3: (p2.y, p2.z, p2.w), coord (c1.z, c1.w)
    apply_one(p2.y, p2.z, p2.w, c1.z, c1.w, grid, o2.y, o2.z, o2.w);

    out[q * 3 + 0] = o0;
    out[q * 3 + 1] = o1;
    out[q * 3 + 2] = o2;
}

extern "C" void kernel_launch(void* const* d_in, const int* in_sizes, int n_in,
                              void* d_out, int out_size)
{
    const float* pixels = (const float*)d_in[0];  // N*3
    const float* coords = (const float*)d_in[1];  // N*2
    const float* grid   = (const float*)d_in[2];  // 16*16*8*12

    int n_pixels = in_sizes[0] / 3;
    int nquads = n_pixels / 4;   // 8,294,400 / 4 = 2,073,600 (exact)

    int threads = 256;
    int blocks = (nquads + threads - 1) / threads;

    bilateral_grid_kernel<<<blocks, threads>>>(
        (const float4*)pixels, (const float4*)coords, grid,
        (float4*)d_out, nquads);
}

// round 3
// speedup vs baseline: 1.0161x; 1.0161x over previous
#include <cuda_runtime.h>

// BilateralGrid apply. pixels (B,H,W,3) f32, coords (B,H,W,2) f32,
// grid (16,16,8,12) f32 = 96 KB -> staged in dynamic shared memory.
// Coord/guide addresses are fully random, so corner gathers go through the
// SMEM crossbar (no 128B-line granularity waste) instead of L1 wavefronts.

static constexpr int SH = 16;
static constexpr int SW = 16;
static constexpr int SL = 8;
static constexpr int GRID_FLOATS = SH * SW * SL * 12;      // 24576
static constexpr int GRID_BYTES  = GRID_FLOATS * 4;        // 98304

// clip guarantees x0<=14, y0<=14, z0<=6 -> +1 never needs clamping.
// offsets in floats from base record (((y*16+x)*8)+z)*12:
//   z+1 : +12,  x+1 : +96,  y+1 : +1536
static __device__ __forceinline__ void apply_one(
    float r, float g, float b, float cx, float cy,
    const float* __restrict__ sgrid,
    float& or_, float& og_, float& ob_)
{
    float guide = 0.2126f * r + 0.7152f * g + 0.0722f * b;

    float gx = fminf(fmaxf(cx * (SW - 1), 0.0f), SW - 1.001f);
    float gy = fminf(fmaxf(cy * (SH - 1), 0.0f), SH - 1.001f);
    float gcl = fminf(fmaxf(guide, 0.0f), 1.0f);
    float gz = fminf(fmaxf(gcl * (SL - 1), 0.0f), SL - 1.001f);

    int x0 = (int)gx;
    int y0 = (int)gy;
    int z0 = (int)gz;

    float fx = gx - (float)x0;
    float fy = gy - (float)y0;
    float fz = gz - (float)z0;
    float ex = 1.0f - fx, ey = 1.0f - fy, ez = 1.0f - fz;

    // 8 trilinear weights
    float wa = ey * ex, wb = ey * fx, wc = fy * ex, wd = fy * fx;
    float w000 = wa * ez, w001 = wa * fz;
    float w010 = wb * ez, w011 = wb * fz;
    float w100 = wc * ez, w101 = wc * fz;
    float w110 = wd * ez, w111 = wd * fz;

    int base = ((y0 * SW + x0) * SL + z0) * 12;

    float a0 = 0.f, a1 = 0.f, a2 = 0.f, a3 = 0.f;
    float a4 = 0.f, a5 = 0.f, a6 = 0.f, a7 = 0.f;
    float a8 = 0.f, a9 = 0.f, a10 = 0.f, a11 = 0.f;

#define CORNER(OFF, Wt)                                                        \
    {                                                                          \
        const float4* cp = (const float4*)(sgrid + base + (OFF));              \
        float4 qa = cp[0];                                                     \
        float4 qb = cp[1];                                                     \
        float4 qc = cp[2];                                                     \
        float w = (Wt);                                                        \
        a0 += w * qa.x;  a1 += w * qa.y;  a2  += w * qa.z;  a3  += w * qa.w;   \
        a4 += w * qb.x;  a5 += w * qb.y;  a6  += w * qb.z;  a7  += w * qb.w;   \
        a8 += w * qc.x;  a9 += w * qc.y;  a10 += w * qc.z;  a11 += w * qc.w;   \
    }

    CORNER(0,           w000);
    CORNER(12,          w001);
    CORNER(96,          w010);
    CORNER(96 + 12,     w011);
    CORNER(1536,        w100);
    CORNER(1536 + 12,   w101);
    CORNER(1536 + 96,   w110);
    CORNER(1536 + 108,  w111);
#undef CORNER

    or_ = a0 * r + a1 * g + a2 * b + a3;
    og_ = a4 * r + a5 * g + a6 * b + a7;
    ob_ = a8 * r + a9 * g + a10 * b + a11;
}

__global__ void __launch_bounds__(256, 2)
bilateral_grid_kernel(const float4* __restrict__ px,   // 3 float4 per quad
                      const float4* __restrict__ cd,   // 2 float4 per quad
                      const float* __restrict__ grid,
                      float4* __restrict__ out,        // 3 float4 per quad
                      int nquads)
{
    extern __shared__ float sgrid[];

    // Stage the 96 KB grid: 6144 float4, 256 threads -> 24 iters, coalesced.
    {
        const float4* gsrc = (const float4*)grid;
        float4* gdst = (float4*)sgrid;
        #pragma unroll
        for (int i = 0; i < GRID_FLOATS / 4 / 256; i++)
            gdst[threadIdx.x + i * 256] = gsrc[threadIdx.x + i * 256];
    }
    __syncthreads();

    int stride = gridDim.x * blockDim.x;

    for (int q = blockIdx.x * blockDim.x + threadIdx.x; q < nquads; q += stride) {
        float4 p0 = px[q * 3 + 0];
        float4 p1 = px[q * 3 + 1];
        float4 p2 = px[q * 3 + 2];
        float4 c0 = cd[q * 2 + 0];
        float4 c1 = cd[q * 2 + 1];

        float4 o0, o1, o2;

        apply_one(p0.x, p0.y, p0.z, c0.x, c0.y, sgrid, o0.x, o0.y, o0.z);
        apply_one(p0.w, p1.x, p1.y, c0.z, c0.w, sgrid, o0.w, o1.x, o1.y);
        apply_one(p1.z, p1.w, p2.x, c1.x, c1.y, sgrid, o1.z, o1.w, o2.x);
        apply_one(p2.y, p2.z, p2.w, c1.z, c1.w, sgrid, o2.y, o2.z, o2.w);

        out[q * 3 + 0] = o0;
        out[q * 3 + 1] = o1;
        out[q * 3 + 2] = o2;
    }
}

extern "C" void kernel_launch(void* const* d_in, const int* in_sizes, int n_in,
                              void* d_out, int out_size)
{
    const float* pixels = (const float*)d_in[0];  // N*3
    const float* coords = (const float*)d_in[1];  // N*2
    const float* grid   = (const float*)d_in[2];  // 16*16*8*12

    int n_pixels = in_sizes[0] / 3;
    int nquads = n_pixels / 4;     // 2,073,600

    cudaFuncSetAttribute(bilateral_grid_kernel,
                         cudaFuncAttributeMaxDynamicSharedMemorySize, GRID_BYTES);

    // 2 CTAs/SM * 148 SMs = 296 resident; 592 blocks = 2 balanced waves.
    int threads = 256;
    int blocks = 592;

    bilateral_grid_kernel<<<blocks, threads, GRID_BYTES>>>(
        (const float4*)pixels, (const float4*)coords, grid,
        (float4*)d_out, nquads);
}

// round 4
// speedup vs baseline: 2.0798x; 2.0469x over previous
#include <cuda_runtime.h>
#include <cuda_fp16.h>

// BilateralGrid apply, fp16 z-interleaved grid gather.
// grid (16,16,8,12) f32 is converted per-launch into
//   g_conv[y][x][z][j] = half2( g[y,x,z,j], g[y,x,z+1,j] ),  z in [0,7)
// so one 48B record provides BOTH z-corners -> 4 gathers/pixel instead of 8,
// halving l1tex gather traffic (the measured bottleneck). All arithmetic fp32.

static constexpr int SH = 16;
static constexpr int SW = 16;
static constexpr int SL = 8;
static constexpr int ZI = SL - 1;                      // 7 interleaved z slots
static constexpr int CONV_ELEMS = SH * SW * ZI * 12;   // 21504 half2
static constexpr int CONV_BYTES = CONV_ELEMS * 4;      // 86016 B

__device__ __align__(16) __half2 g_conv[CONV_ELEMS];

__global__ void convert_grid_kernel(const float* __restrict__ grid)
{
    int i = blockIdx.x * blockDim.x + threadIdx.x;
    if (i >= CONV_ELEMS) return;
    int j  = i % 12;
    int t  = i / 12;
    int z  = t % ZI;
    int yx = t / ZI;                      // y*16 + x
    const float* rec = grid + ((yx * SL + z) * 12) + j;
    g_conv[i] = __floats2half2_rn(rec[0], rec[12]);   // (z, z+1)
}

static __device__ __forceinline__ void apply_one(
    float r, float g, float b, float cx, float cy,
    const __half2* __restrict__ sg,
    float& or_, float& og_, float& ob_)
{
    float guide = 0.2126f * r + 0.7152f * g + 0.0722f * b;

    float gx = fminf(fmaxf(cx * (SW - 1), 0.0f), SW - 1.001f);
    float gy = fminf(fmaxf(cy * (SH - 1), 0.0f), SH - 1.001f);
    float gcl = fminf(fmaxf(guide, 0.0f), 1.0f);
    float gz = fminf(fmaxf(gcl * (SL - 1), 0.0f), SL - 1.001f);

    int x0 = (int)gx;
    int y0 = (int)gy;
    int z0 = (int)gz;     // 0..6

    float fx = gx - (float)x0;
    float fy = gy - (float)y0;
    float fz = gz - (float)z0;
    float ex = 1.0f - fx, ey = 1.0f - fy, ez = 1.0f - fz;

    // 2D (y,x) corner weights; z handled inside each record.
    float w00 = ey * ex, w01 = ey * fx, w10 = fy * ex, w11 = fy * fx;

    int base = ((y0 * SW + x0) * ZI + z0) * 12;   // half2 units

    float a0 = 0.f, a1 = 0.f, a2 = 0.f, a3 = 0.f;
    float a4 = 0.f, a5 = 0.f, a6 = 0.f, a7 = 0.f;
    float a8 = 0.f, a9 = 0.f, a10 = 0.f, a11 = 0.f;

#define CORNER(OFF, Wyx)                                                       \
    {                                                                          \
        const uint4* cp = (const uint4*)(sg + base + (OFF));                   \
        uint4 qa = cp[0];                                                      \
        uint4 qb = cp[1];                                                      \
        uint4 qc = cp[2];                                                      \
        float wz0 = (Wyx) * ez;                                                \
        float wz1 = (Wyx) * fz;                                                \
        const __half2* h = (const __half2*)&qa;                                \
        a0 += wz0 * __low2float(h[0]) + wz1 * __high2float(h[0]);              \
        a1 += wz0 * __low2float(h[1]) + wz1 * __high2float(h[1]);              \
        a2 += wz0 * __low2float(h[2]) + wz1 * __high2float(h[2]);              \
        a3 += wz0 * __low2float(h[3]) + wz1 * __high2float(h[3]);              \
        h = (const __half2*)&qb;                                               \
        a4 += wz0 * __low2float(h[0]) + wz1 * __high2float(h[0]);              \
        a5 += wz0 * __low2float(h[1]) + wz1 * __high2float(h[1]);              \
        a6 += wz0 * __low2float(h[2]) + wz1 * __high2float(h[2]);              \
        a7 += wz0 * __low2float(h[3]) + wz1 * __high2float(h[3]);              \
        h = (const __half2*)&qc;                                               \
        a8  += wz0 * __low2float(h[0]) + wz1 * __high2float(h[0]);             \
        a9  += wz0 * __low2float(h[1]) + wz1 * __high2float(h[1]);             \
        a10 += wz0 * __low2float(h[2]) + wz1 * __high2float(h[2]);             \
        a11 += wz0 * __low2float(h[3]) + wz1 * __high2float(h[3]);             \
    }

    CORNER(0,            w00);            // (y0, x0)
    CORNER(ZI * 12,      w01);            // (y0, x1)  +84
    CORNER(SW * ZI * 12, w10);            // (y1, x0)  +1344
    CORNER(SW * ZI * 12 + ZI * 12, w11);  // (y1, x1)  +1428
#undef CORNER

    or_ = a0 * r + a1 * g + a2 * b + a3;
    og_ = a4 * r + a5 * g + a6 * b + a7;
    ob_ = a8 * r + a9 * g + a10 * b + a11;
}

__global__ void __launch_bounds__(256, 2)
bilateral_grid_kernel(const float4* __restrict__ px,   // 3 float4 per quad
                      const float4* __restrict__ cd,   // 2 float4 per quad
                      float4* __restrict__ out,        // 3 float4 per quad
                      int nquads)
{
    extern __shared__ __half2 sg[];

    // Stage 84 KB converted grid: 5376 uint4, 256 threads -> 21 iters.
    {
        const uint4* src = (const uint4*)g_conv;
        uint4* dst = (uint4*)sg;
        #pragma unroll
        for (int i = 0; i < CONV_BYTES / 16 / 256; i++)
            dst[threadIdx.x + i * 256] = src[threadIdx.x + i * 256];
    }
    __syncthreads();

    int stride = gridDim.x * blockDim.x;

    for (int q = blockIdx.x * blockDim.x + threadIdx.x; q < nquads; q += stride) {
        float4 p0 = px[q * 3 + 0];
        float4 p1 = px[q * 3 + 1];
        float4 p2 = px[q * 3 + 2];
        float4 c0 = cd[q * 2 + 0];
        float4 c1 = cd[q * 2 + 1];

        float4 o0, o1, o2;

        apply_one(p0.x, p0.y, p0.z, c0.x, c0.y, sg, o0.x, o0.y, o0.z);
        apply_one(p0.w, p1.x, p1.y, c0.z, c0.w, sg, o0.w, o1.x, o1.y);
        apply_one(p1.z, p1.w, p2.x, c1.x, c1.y, sg, o1.z, o1.w, o2.x);
        apply_one(p2.y, p2.z, p2.w, c1.z, c1.w, sg, o2.y, o2.z, o2.w);

        out[q * 3 + 0] = o0;
        out[q * 3 + 1] = o1;
        out[q * 3 + 2] = o2;
    }
}

extern "C" void kernel_launch(void* const* d_in, const int* in_sizes, int n_in,
                              void* d_out, int out_size)
{
    const float* pixels = (const float*)d_in[0];  // N*3
    const float* coords = (const float*)d_in[1];  // N*2
    const float* grid   = (const float*)d_in[2];  // 16*16*8*12

    int n_pixels = in_sizes[0] / 3;
    int nquads = n_pixels / 4;     // 2,073,600

    convert_grid_kernel<<<(CONV_ELEMS + 255) / 256, 256>>>(grid);

    cudaFuncSetAttribute(bilateral_grid_kernel,
                         cudaFuncAttributeMaxDynamicSharedMemorySize, CONV_BYTES);

    bilateral_grid_kernel<<<592, 256, CONV_BYTES>>>(
        (const float4*)pixels, (const float4*)coords,
        (float4*)d_out, nquads);
}

// round 5
// speedup vs baseline: 2.1050x; 1.0121x over previous
#include <cuda_runtime.h>
#include <cuda_fp16.h>

// BilateralGrid apply, fp16 z-interleaved grid gather + half2 corner accumulation.
// grid (16,16,8,12) f32 -> g_conv[y][x][z][j] = half2(g[y,x,z,j], g[y,x,z+1,j]), z in [0,7)
// Per pixel: 4 corner records (48 B each) gathered from SMEM; the 4-corner
// (y,x) bilinear reduction runs in half2 (z0/z1 in the two lanes, 48 HFMA2),
// then one fp32 z-combine per coefficient. Affine apply in fp32.

static constexpr int SH = 16;
static constexpr int SW = 16;
static constexpr int SL = 8;
static constexpr int ZI = SL - 1;                      // 7 interleaved z slots
static constexpr int CONV_ELEMS = SH * SW * ZI * 12;   // 21504 half2
static constexpr int CONV_BYTES = CONV_ELEMS * 4;      // 86016 B

__device__ __align__(16) __half2 g_conv[CONV_ELEMS];

__global__ void convert_grid_kernel(const float* __restrict__ grid)
{
    int i = blockIdx.x * blockDim.x + threadIdx.x;
    if (i >= CONV_ELEMS) return;
    int j  = i % 12;
    int t  = i / 12;
    int z  = t % ZI;
    int yx = t / ZI;                      // y*16 + x
    const float* rec = grid + ((yx * SL + z) * 12) + j;
    g_conv[i] = __floats2half2_rn(rec[0], rec[12]);   // (z, z+1)
}

static __device__ __forceinline__ void apply_one(
    float r, float g, float b, float cx, float cy,
    const __half2* __restrict__ sg,
    float& or_, float& og_, float& ob_)
{
    float guide = 0.2126f * r + 0.7152f * g + 0.0722f * b;

    float gx = fminf(fmaxf(cx * (SW - 1), 0.0f), SW - 1.001f);
    float gy = fminf(fmaxf(cy * (SH - 1), 0.0f), SH - 1.001f);
    float gcl = fminf(fmaxf(guide, 0.0f), 1.0f);
    float gz = fminf(fmaxf(gcl * (SL - 1), 0.0f), SL - 1.001f);

    int x0 = (int)gx;
    int y0 = (int)gy;
    int z0 = (int)gz;     // 0..6

    float fx = gx - (float)x0;
    float fy = gy - (float)y0;
    float fz = gz - (float)z0;
    float ex = 1.0f - fx, ey = 1.0f - fy, ez = 1.0f - fz;

    // (y,x) corner weights, broadcast to both half2 lanes (z handled in lanes).
    __half2 hw00 = __float2half2_rn(ey * ex);
    __half2 hw01 = __float2half2_rn(ey * fx);
    __half2 hw10 = __float2half2_rn(fy * ex);
    __half2 hw11 = __float2half2_rn(fy * fx);

    int base = ((y0 * SW + x0) * ZI + z0) * 12;   // half2 units

    __half2 A0, A1, A2, A3, A4, A5, A6, A7, A8, A9, A10, A11;

#define CORNER_FIRST(OFF, HW)                                                  \
    {                                                                          \
        const uint4* cp = (const uint4*)(sg + base + (OFF));                   \
        uint4 qa = cp[0]; uint4 qb = cp[1]; uint4 qc = cp[2];                  \
        const __half2* h = (const __half2*)&qa;                                \
        A0 = __hmul2(HW, h[0]); A1 = __hmul2(HW, h[1]);                        \
        A2 = __hmul2(HW, h[2]); A3 = __hmul2(HW, h[3]);                        \
        h = (const __half2*)&qb;                                               \
        A4 = __hmul2(HW, h[0]); A5 = __hmul2(HW, h[1]);                        \
        A6 = __hmul2(HW, h[2]); A7 = __hmul2(HW, h[3]);                        \
        h = (const __half2*)&qc;                                               \
        A8 = __hmul2(HW, h[0]); A9 = __hmul2(HW, h[1]);                        \
        A10 = __hmul2(HW, h[2]); A11 = __hmul2(HW, h[3]);                      \
    }

#define CORNER(OFF, HW)                                                        \
    {                                                                          \
        const uint4* cp = (const uint4*)(sg + base + (OFF));                   \
        uint4 qa = cp[0]; uint4 qb = cp[1]; uint4 qc = cp[2];                  \
        const __half2* h = (const __half2*)&qa;                                \
        A0 = __hfma2(HW, h[0], A0); A1 = __hfma2(HW, h[1], A1);                \
        A2 = __hfma2(HW, h[2], A2); A3 = __hfma2(HW, h[3], A3);                \
        h = (const __half2*)&qb;                                               \
        A4 = __hfma2(HW, h[0], A4); A5 = __hfma2(HW, h[1], A5);                \
        A6 = __hfma2(HW, h[2], A6); A7 = __hfma2(HW, h[3], A7);                \
        h = (const __half2*)&qc;                                               \
        A8 = __hfma2(HW, h[0], A8); A9 = __hfma2(HW, h[1], A9);                \
        A10 = __hfma2(HW, h[2], A10); A11 = __hfma2(HW, h[3], A11);            \
    }

    CORNER_FIRST(0,                        hw00);   // (y0, x0)
    CORNER      (ZI * 12,                  hw01);   // (y0, x1)
    CORNER      (SW * ZI * 12,             hw10);   // (y1, x0)
    CORNER      (SW * ZI * 12 + ZI * 12,   hw11);   // (y1, x1)
#undef CORNER
#undef CORNER_FIRST

    // fp32 z-combine: a_j = lo*ez + hi*fz
#define ZC(AH) ({ float2 f_ = __half22float2(AH); f_.x * ez + f_.y * fz; })
    float a0 = ZC(A0), a1 = ZC(A1), a2 = ZC(A2), a3 = ZC(A3);
    float a4 = ZC(A4), a5 = ZC(A5), a6 = ZC(A6), a7 = ZC(A7);
    float a8 = ZC(A8), a9 = ZC(A9), a10 = ZC(A10), a11 = ZC(A11);
#undef ZC

    or_ = a0 * r + a1 * g + a2 * b + a3;
    og_ = a4 * r + a5 * g + a6 * b + a7;
    ob_ = a8 * r + a9 * g + a10 * b + a11;
}

__global__ void __launch_bounds__(256, 2)
bilateral_grid_kernel(const float4* __restrict__ px,   // 3 float4 per quad
                      const float4* __restrict__ cd,   // 2 float4 per quad
                      float4* __restrict__ out,        // 3 float4 per quad
                      int nquads)
{
    extern __shared__ __half2 sg[];

    // Stage 84 KB converted grid: 5376 uint4, 256 threads -> 21 iters.
    {
        const uint4* src = (const uint4*)g_conv;
        uint4* dst = (uint4*)sg;
        #pragma unroll
        for (int i = 0; i < CONV_BYTES / 16 / 256; i++)
            dst[threadIdx.x + i * 256] = src[threadIdx.x + i * 256];
    }
    __syncthreads();

    int stride = gridDim.x * blockDim.x;

    for (int q = blockIdx.x * blockDim.x + threadIdx.x; q < nquads; q += stride) {
        float4 p0 = px[q * 3 + 0];
        float4 p1 = px[q * 3 + 1];
        float4 p2 = px[q * 3 + 2];
        float4 c0 = cd[q * 2 + 0];
        float4 c1 = cd[q * 2 + 1];

        float4 o0, o1, o2;

        apply_one(p0.x, p0.y, p0.z, c0.x, c0.y, sg, o0.x, o0.y, o0.z);
        apply_one(p0.w, p1.x, p1.y, c0.z, c0.w, sg, o0.w, o1.x, o1.y);
        apply_one(p1.z, p1.w, p2.x, c1.x, c1.y, sg, o1.z, o1.w, o2.x);
        apply_one(p2.y, p2.z, p2.w, c1.z, c1.w, sg, o2.y, o2.z, o2.w);

        out[q * 3 + 0] = o0;
        out[q * 3 + 1] = o1;
        out[q * 3 + 2] = o2;
    }
}

extern "C" void kernel_launch(void* const* d_in, const int* in_sizes, int n_in,
                              void* d_out, int out_size)
{
    const float* pixels = (const float*)d_in[0];  // N*3
    const float* coords = (const float*)d_in[1];  // N*2
    const float* grid   = (const float*)d_in[2];  // 16*16*8*12

    int n_pixels = in_sizes[0] / 3;
    int nquads = n_pixels / 4;     // 2,073,600

    convert_grid_kernel<<<(CONV_ELEMS + 255) / 256, 256>>>(grid);

    cudaFuncSetAttribute(bilateral_grid_kernel,
                         cudaFuncAttributeMaxDynamicSharedMemorySize, CONV_BYTES);

    bilateral_grid_kernel<<<592, 256, CONV_BYTES>>>(
        (const float4*)pixels, (const float4*)coords,
        (float4*)d_out, nquads);
}